// round 9
// baseline (speedup 1.0000x reference)
#include <cuda_runtime.h>
#include <cstdint>

// SigCubicalEcc round 9 = round 8 formula, restructured for issue-count:
//   SPG=4 (row overhead + EX2 amortized over 4 steps), 128-thread blocks,
//   4 warps x 16 rows (halo overhead 17/16), grid 1536 ~= one wave.
//
// ECC_j = Sum_v max(m, m_up) - Sum_eh max(s, s_up) - Sum_ev m + Sum_f s
// s = sigma(lam*(t_j - x)) per pixel, m = horizontal pair max; zero padding.
// sigma(lam(t-x)) = rcp(1 + ex2(K*x) * 2^{-K*t}),  K = LAM*log2(e).
// Overflow exact: ex2->inf, fma->inf, rcp.approx(inf)=0.

#define HH 64
#define WW 64
#define STEPS 32
#define GROUPS 8
#define SPG (STEPS / GROUPS)    // 4 steps per block
#define THREADS 128
#define NWARP 4
#define ROWS_PER_WARP 16
#define NIMG 192

__device__ __forceinline__ float ex2_approx(float x) {
    float y;
    asm("ex2.approx.ftz.f32 %0, %1;" : "=f"(y) : "f"(x));
    return y;
}
__device__ __forceinline__ float rcp_approx(float x) {
    float y;
    asm("rcp.approx.ftz.f32 %0, %1;" : "=f"(y) : "f"(x));
    return y;
}

__global__ __launch_bounds__(THREADS, 11)
void sig_cubical_ecc_kernel(const float* __restrict__ x, float* __restrict__ out) {
    __shared__ float red[NWARP][SPG];

    const int img   = blockIdx.x >> 3;           // / GROUPS
    const int group = blockIdx.x & (GROUPS - 1);
    const int tid   = threadIdx.x;
    const int lane  = tid & 31;
    const int warp  = tid >> 5;

    const float K = 200.0f * 1.4426950408889634f;   // LAM * log2(e)

    // c_j = 2^(-K * t_j) for this block's steps
    float cj[SPG];
#pragma unroll
    for (int jj = 0; jj < SPG; jj++) {
        int j = group * SPG + jj;
        float tj = 0.02f + (float)j * (0.26f / 31.0f);
        cj[jj] = ex2_approx(-K * tj);
    }

    const float* xi = x + (size_t)img * (HH * WW) + 2 * lane;
    const int r0 = warp * ROWS_PER_WARP;

    float sp0[SPG], sp1[SPG], mp0[SPG], mp1[SPG], acc[SPG];
#pragma unroll
    for (int jj = 0; jj < SPG; jj++) {
        sp0[jj] = 0.0f; sp1[jj] = 0.0f;
        mp0[jj] = 0.0f; mp1[jj] = 0.0f;
        acc[jj] = 0.0f;
    }

    // ---- halo row r0-1 (warp 0: row -1 is padding => all zeros) ----
    if (warp > 0) {
        float2 xv = *reinterpret_cast<const float2*>(xi + (r0 - 1) * WW);
        float ex = ex2_approx(xv.x * K);
        float ey = ex2_approx(xv.y * K);
#pragma unroll
        for (int jj = 0; jj < SPG; jj++) {
            float s0 = rcp_approx(fmaf(ex, cj[jj], 1.0f));
            float s1 = rcp_approx(fmaf(ey, cj[jj], 1.0f));
            float sn = __shfl_down_sync(0xffffffffu, s0, 1);
            sn = (lane == 31) ? 0.0f : sn;
            sp0[jj] = s0; sp1[jj] = s1;
            mp0[jj] = fmaxf(s0, s1);
            mp1[jj] = fmaxf(s1, sn);
        }
    }

    // ---- 16 data rows ----
#pragma unroll 4
    for (int i = 0; i < ROWS_PER_WARP; i++) {
        float2 xv = *reinterpret_cast<const float2*>(xi + (r0 + i) * WW);
        float ex = ex2_approx(xv.x * K);
        float ey = ex2_approx(xv.y * K);
#pragma unroll
        for (int jj = 0; jj < SPG; jj++) {
            float s0 = rcp_approx(fmaf(ex, cj[jj], 1.0f));
            float s1 = rcp_approx(fmaf(ey, cj[jj], 1.0f));
            float sn = __shfl_down_sync(0xffffffffu, s0, 1);
            sn = (lane == 31) ? 0.0f : sn;
            float m0 = fmaxf(s0, s1);
            float m1 = fmaxf(s1, sn);

            float eh    = fmaxf(s0, sp0[jj]);
            float ehsel = (lane == 0) ? s0 : eh;   // left-boundary cancellation
            acc[jj] += (fminf(s0, s1) - m1)
                     + (fmaxf(m0, mp0[jj]) - ehsel)
                     + (fmaxf(m1, mp1[jj]) - fmaxf(s1, sp1[jj]));

            sp0[jj] = s0; sp1[jj] = s1; mp0[jj] = m0; mp1[jj] = m1;
        }
    }

    // ---- bottom boundary (vertex row 64): the row below is all zeros ----
    if (warp == NWARP - 1) {
#pragma unroll
        for (int jj = 0; jj < SPG; jj++) {
            float ehsel = (lane == 0) ? 0.0f : sp0[jj];
            acc[jj] += (mp0[jj] - ehsel) + (mp1[jj] - sp1[jj]);
        }
    }

    // ---- warp reduce, then block reduce in smem, single store ----
#pragma unroll
    for (int jj = 0; jj < SPG; jj++) {
        float v = acc[jj];
#pragma unroll
        for (int o = 16; o > 0; o >>= 1)
            v += __shfl_xor_sync(0xffffffffu, v, o);
        if (lane == 0) red[warp][jj] = v;
    }
    __syncthreads();

    if (tid < SPG) {
        float s = 0.0f;
#pragma unroll
        for (int w = 0; w < NWARP; w++) s += red[w][tid];
        out[img * STEPS + group * SPG + tid] = s;
    }
}

extern "C" void kernel_launch(void* const* d_in, const int* in_sizes, int n_in,
                              void* d_out, int out_size) {
    const float* x = (const float*)d_in[0];
    float* out = (float*)d_out;

    sig_cubical_ecc_kernel<<<NIMG * GROUPS, THREADS>>>(x, out);
}

// round 10
// speedup vs baseline: 1.1196x; 1.1196x over previous
#include <cuda_runtime.h>
#include <cstdint>

// SigCubicalEcc round 10 = round 8 structure with sigmoid -> tanh.approx.
// h = tanh(100*(t_j - x)) = 2*sigma - 1; monotone, so the max-decomposition
// is formally identical with padding h = -1, and
//   ECC_j = 0.5 * [signed sum of h over cells] + 0.5*(V-Eh-Ev+F) ; V-Eh-Ev+F = 1.
// One MUFU (TANH) per pixel-step, zero EX2. 256 thr, 8 warps x 8 rows, SPG=2.

#define HH 64
#define WW 64
#define STEPS 32
#define GROUPS 16
#define SPG (STEPS / GROUPS)    // 2 steps per block
#define THREADS 256
#define NWARP 8
#define ROWS_PER_WARP 8
#define NIMG 192

__device__ __forceinline__ float tanh_approx(float x) {
    float y;
    asm("tanh.approx.f32 %0, %1;" : "=f"(y) : "f"(x));
    return y;
}

__global__ __launch_bounds__(THREADS, 8)
void sig_cubical_ecc_kernel(const float* __restrict__ x, float* __restrict__ out) {
    __shared__ float red[NWARP][SPG];

    const int img   = blockIdx.x >> 4;           // / GROUPS
    const int group = blockIdx.x & (GROUPS - 1);
    const int tid   = threadIdx.x;
    const int lane  = tid & 31;
    const int warp  = tid >> 5;

    const float HL = 100.0f;                     // LAM / 2

    // A_j = 100 * t_j for this block's steps (compile/immediate constants)
    float Aj[SPG];
#pragma unroll
    for (int jj = 0; jj < SPG; jj++) {
        int j = group * SPG + jj;
        float tj = 0.02f + (float)j * (0.26f / 31.0f);
        Aj[jj] = HL * tj;
    }

    const float* xi = x + (size_t)img * (HH * WW) + 2 * lane;
    const int r0 = warp * ROWS_PER_WARP;

    float sp0[SPG], sp1[SPG], mp0[SPG], mp1[SPG], acc[SPG];
#pragma unroll
    for (int jj = 0; jj < SPG; jj++) {
        sp0[jj] = -1.0f; sp1[jj] = -1.0f;        // padding: h = -1
        mp0[jj] = -1.0f; mp1[jj] = -1.0f;
        acc[jj] = 0.0f;
    }

    // ---- halo row r0-1 (warp 0: row -1 is padding => h = -1, keep init) ----
    if (warp > 0) {
        float2 xv = *reinterpret_cast<const float2*>(xi + (r0 - 1) * WW);
        float g0 = xv.x * HL;
        float g1 = xv.y * HL;
#pragma unroll
        for (int jj = 0; jj < SPG; jj++) {
            float s0 = tanh_approx(Aj[jj] - g0);
            float s1 = tanh_approx(Aj[jj] - g1);
            float sn = __shfl_down_sync(0xffffffffu, s0, 1);
            sn = (lane == 31) ? -1.0f : sn;      // right pad: h = -1
            sp0[jj] = s0; sp1[jj] = s1;
            mp0[jj] = fmaxf(s0, s1);
            mp1[jj] = fmaxf(s1, sn);
        }
    }

    // ---- 8 data rows ----
#pragma unroll
    for (int i = 0; i < ROWS_PER_WARP; i++) {
        float2 xv = *reinterpret_cast<const float2*>(xi + (r0 + i) * WW);
        float g0 = xv.x * HL;
        float g1 = xv.y * HL;
#pragma unroll
        for (int jj = 0; jj < SPG; jj++) {
            float s0 = tanh_approx(Aj[jj] - g0);
            float s1 = tanh_approx(Aj[jj] - g1);
            float sn = __shfl_down_sync(0xffffffffu, s0, 1);
            sn = (lane == 31) ? -1.0f : sn;      // right pad: h = -1
            float m0 = fmaxf(s0, s1);
            float m1 = fmaxf(s1, sn);

            float eh    = fmaxf(s0, sp0[jj]);
            float ehsel = (lane == 0) ? s0 : eh; // left-boundary cancellation
            acc[jj] += (fminf(s0, s1) - m1)
                     + (fmaxf(m0, mp0[jj]) - ehsel)
                     + (fmaxf(m1, mp1[jj]) - fmaxf(s1, sp1[jj]));

            sp0[jj] = s0; sp1[jj] = s1; mp0[jj] = m0; mp1[jj] = m1;
        }
    }

    // ---- bottom boundary (vertex/h-edge row 64): row below has h = -1 ----
    if (warp == NWARP - 1) {
#pragma unroll
        for (int jj = 0; jj < SPG; jj++) {
            float ehsel = (lane == 0) ? 0.0f : sp0[jj];
            acc[jj] += (mp0[jj] - ehsel) + (mp1[jj] - sp1[jj]);
        }
    }

    // ---- warp reduce, then block reduce in smem, single store ----
#pragma unroll
    for (int jj = 0; jj < SPG; jj++) {
        float v = acc[jj];
#pragma unroll
        for (int o = 16; o > 0; o >>= 1)
            v += __shfl_xor_sync(0xffffffffu, v, o);
        if (lane == 0) red[warp][jj] = v;
    }
    __syncthreads();

    if (tid < SPG) {
        float s = 0.0f;
#pragma unroll
        for (int w = 0; w < NWARP; w++) s += red[w][tid];
        // ECC = 0.5 * signed h-sum + 0.5 * (V - Eh - Ev + F), chi count = 1
        out[img * STEPS + group * SPG + tid] = 0.5f * s + 0.5f;
    }
}

extern "C" void kernel_launch(void* const* d_in, const int* in_sizes, int n_in,
                              void* d_out, int out_size) {
    const float* x = (const float*)d_in[0];
    float* out = (float*)d_out;

    sig_cubical_ecc_kernel<<<NIMG * GROUPS, THREADS>>>(x, out);
}

// round 12
// speedup vs baseline: 1.5013x; 1.3409x over previous
#include <cuda_runtime.h>
#include <cuda_fp16.h>
#include <cstdint>

// SigCubicalEcc round 12 = round 11 (half2-packed step pair) with the dead
// helper that broke compilation removed.
//
// h = tanh(100*(t_j - x)) = 2*sigma - 1 (monotone => max-decomposition holds
// with padding h = -1):
//   ECC_j = 0.5 * [signed h-sum over cells] + 0.5.
// tanh in f32, packed to half2 for the min/max chain, f32 accumulation per row.
// 256 thr, 8 warps x 8 rows, GROUPS=16 (SPG=2 packed), single launch.

#define HH 64
#define WW 64
#define STEPS 32
#define GROUPS 16
#define SPG 2                   // 2 steps, packed in one half2
#define THREADS 256
#define NWARP 8
#define ROWS_PER_WARP 8
#define NIMG 192

__device__ __forceinline__ float tanh_approx(float x) {
    float y;
    asm("tanh.approx.f32 %0, %1;" : "=f"(y) : "f"(x));
    return y;
}

__device__ __forceinline__ uint32_t h2_as_u32(__half2 v) {
    return *reinterpret_cast<uint32_t*>(&v);
}
__device__ __forceinline__ __half2 u32_as_h2(uint32_t u) {
    return *reinterpret_cast<__half2*>(&u);
}

__global__ __launch_bounds__(THREADS, 8)
void sig_cubical_ecc_kernel(const float* __restrict__ x, float* __restrict__ out) {
    __shared__ float red[NWARP][SPG];

    const int img   = blockIdx.x >> 4;           // / GROUPS
    const int group = blockIdx.x & (GROUPS - 1);
    const int tid   = threadIdx.x;
    const int lane  = tid & 31;
    const int warp  = tid >> 5;

    const float HL = 100.0f;                     // LAM / 2

    // A_j = 100 * t_j for this block's two steps
    const int j0 = group * SPG;
    const float A0 = HL * (0.02f + (float)(j0 + 0) * (0.26f / 31.0f));
    const float A1 = HL * (0.02f + (float)(j0 + 1) * (0.26f / 31.0f));

    const __half2 NEG1 = __floats2half2_rn(-1.0f, -1.0f);
    const __half2 ZERO = __floats2half2_rn(0.0f, 0.0f);

    const float* xi = x + (size_t)img * (HH * WW) + 2 * lane;
    const int r0 = warp * ROWS_PER_WARP;

    __half2 sp0 = NEG1, sp1 = NEG1, mp0 = NEG1, mp1 = NEG1;  // padding h = -1
    float accx = 0.0f, accy = 0.0f;

    // ---- halo row r0-1 (warp 0: row -1 is padding => keep NEG1 init) ----
    if (warp > 0) {
        float2 xv = *reinterpret_cast<const float2*>(xi + (r0 - 1) * WW);
        float t00 = tanh_approx(fmaf(xv.x, -HL, A0));
        float t01 = tanh_approx(fmaf(xv.x, -HL, A1));
        float t10 = tanh_approx(fmaf(xv.y, -HL, A0));
        float t11 = tanh_approx(fmaf(xv.y, -HL, A1));
        __half2 s0 = __floats2half2_rn(t00, t01);
        __half2 s1 = __floats2half2_rn(t10, t11);
        uint32_t snu = __shfl_down_sync(0xffffffffu, h2_as_u32(s0), 1);
        __half2 sn = (lane == 31) ? NEG1 : u32_as_h2(snu);
        sp0 = s0; sp1 = s1;
        mp0 = __hmax2(s0, s1);
        mp1 = __hmax2(s1, sn);
    }

    // ---- 8 data rows ----
#pragma unroll
    for (int i = 0; i < ROWS_PER_WARP; i++) {
        float2 xv = *reinterpret_cast<const float2*>(xi + (r0 + i) * WW);
        float t00 = tanh_approx(fmaf(xv.x, -HL, A0));
        float t01 = tanh_approx(fmaf(xv.x, -HL, A1));
        float t10 = tanh_approx(fmaf(xv.y, -HL, A0));
        float t11 = tanh_approx(fmaf(xv.y, -HL, A1));
        __half2 s0 = __floats2half2_rn(t00, t01);
        __half2 s1 = __floats2half2_rn(t10, t11);
        uint32_t snu = __shfl_down_sync(0xffffffffu, h2_as_u32(s0), 1);
        __half2 sn = (lane == 31) ? NEG1 : u32_as_h2(snu);

        __half2 m0 = __hmax2(s0, s1);
        __half2 m1 = __hmax2(s1, sn);

        __half2 eh    = __hmax2(s0, sp0);
        __half2 ehsel = (lane == 0) ? s0 : eh;   // left-boundary cancellation
        __half2 contrib =
            __hadd2(__hsub2(__hmin2(s0, s1), m1),
            __hadd2(__hsub2(__hmax2(m0, mp0), ehsel),
                    __hsub2(__hmax2(m1, mp1), __hmax2(s1, sp1))));
        float2 cf = __half22float2(contrib);
        accx += cf.x;
        accy += cf.y;

        sp0 = s0; sp1 = s1; mp0 = m0; mp1 = m1;
    }

    // ---- bottom boundary (row below is padding) ----
    if (warp == NWARP - 1) {
        __half2 ehsel = (lane == 0) ? ZERO : sp0;
        __half2 c = __hadd2(__hsub2(mp0, ehsel), __hsub2(mp1, sp1));
        float2 cf = __half22float2(c);
        accx += cf.x;
        accy += cf.y;
    }

    // ---- warp reduce, then block reduce in smem, single store ----
#pragma unroll
    for (int o = 16; o > 0; o >>= 1) {
        accx += __shfl_xor_sync(0xffffffffu, accx, o);
        accy += __shfl_xor_sync(0xffffffffu, accy, o);
    }
    if (lane == 0) { red[warp][0] = accx; red[warp][1] = accy; }
    __syncthreads();

    if (tid < SPG) {
        float s = 0.0f;
#pragma unroll
        for (int w = 0; w < NWARP; w++) s += red[w][tid];
        // ECC = 0.5 * signed h-sum + 0.5 (V - Eh - Ev + F counts = 1)
        out[img * STEPS + group * SPG + tid] = 0.5f * s + 0.5f;
    }
}

extern "C" void kernel_launch(void* const* d_in, const int* in_sizes, int n_in,
                              void* d_out, int out_size) {
    const float* x = (const float*)d_in[0];
    float* out = (float*)d_out;

    sig_cubical_ecc_kernel<<<NIMG * GROUPS, THREADS>>>(x, out);
}